// round 3
// baseline (speedup 1.0000x reference)
#include <cuda_runtime.h>

#define RS      65        // padded shared row stride (floats)
#define NCONF   64
#define NBATCH  4096

__device__ __forceinline__ float fast_rcp(float x) {
    float r;
    asm("rcp.approx.f32 %0, %1;" : "=f"(r) : "f"(x));
    return r * (2.0f - x * r);   // one Newton step -> ~1 ulp
}

__global__ void __launch_bounds__(256, 2) kinetic_kernel(
    const float* __restrict__ MO,
    const float* __restrict__ d2MO,
    const float* __restrict__ dJdMO,
    const float* __restrict__ d2JMO,
    const int*   __restrict__ cup,
    const int*   __restrict__ cdown,
    float*       __restrict__ out)   // [kinetic (B,NCONF) | det_prod (B,NCONF)]
{
    __shared__ float sM[32 * RS];
    __shared__ float sB[32 * RS];
    __shared__ int   sCfg[2048];

    const int b   = blockIdx.x;
    const int tid = threadIdx.x;

    // ---- stage configs ----
    for (int i = tid; i < 1024; i += 256) {
        sCfg[i]        = cup[i];
        sCfg[1024 + i] = cdown[i];
    }

    // ---- stage MO rows + fused B = d2MO + 2*dJdMO + d2JMO ----
    const size_t base = (size_t)b * 2048;
    const float4* gM = (const float4*)(MO    + base);
    const float4* gX = (const float4*)(d2MO  + base);
    const float4* gY = (const float4*)(dJdMO + base);
    const float4* gZ = (const float4*)(d2JMO + base);
    #pragma unroll
    for (int r = 0; r < 2; ++r) {
        int i   = tid + r * 256;
        int row = i >> 4;
        int c4  = i & 15;
        float4 m = gM[i], x = gX[i], w = gY[i], z = gZ[i];
        float* pm = &sM[row * RS + c4 * 4];
        pm[0] = m.x; pm[1] = m.y; pm[2] = m.z; pm[3] = m.w;
        float* pb = &sB[row * RS + c4 * 4];
        pb[0] = x.x + 2.0f * w.x + z.x;
        pb[1] = x.y + 2.0f * w.y + z.y;
        pb[2] = x.z + 2.0f * w.z + z.z;
        pb[3] = x.w + 2.0f * w.w + z.w;
    }
    __syncthreads();

    // ---- layout: 4 eight-lane groups per warp; each group = one 16x16 system
    //      (2 rows per lane). Segments (0,1)=(up,down) of config 2p, (2,3) of 2p+1.
    const int lane = tid & 31;
    const int warp = tid >> 5;
    const int q    = lane & 7;          // my lane within the 8-lane group
    const int seg  = lane >> 3;         // 0..3
    const int spin = seg & 1;
    const int sub  = seg >> 1;
    const unsigned FULL    = 0xFFFFFFFFu;
    const unsigned segmask = 0xFFu << (seg * 8);
    const int      segbase = seg * 8;

    const float* rM0 = &sM[(spin * 16 + q) * RS];   // row q
    const float* rM1 = rM0 + 8 * RS;                // row q+8
    const float* rB0 = &sB[(spin * 16 + q) * RS];
    const float* rB1 = rB0 + 8 * RS;
    const int*   myCfg = &sCfg[spin * 1024];

    #pragma unroll 1
    for (int it = 0; it < 4; ++it) {
        const int c = (warp + it * 8) * 2 + sub;

        // gather my two rows of A and of B
        float a0[16], a1[16], y0[16], y1[16];
        #pragma unroll
        for (int j = 0; j < 16; ++j) {
            int cj = myCfg[c * 16 + j];
            a0[j] = rM0[cj];  a1[j] = rM1[cj];
            y0[j] = rB0[cj];  y1[j] = rB1[cj];
        }

        // ---- LU with partial pivoting on augmented [A | B], 2 rows/lane ----
        int   piv0 = -1, piv1 = -1;        // step at which each local row pivoted
        int   virt0 = q, virt1 = q + 8;    // virtual positions (parity tracking)
        float det = 1.0f, rd0 = 1.0f, rd1 = 1.0f, t = 0.0f;
        bool  neg = false;

        #pragma unroll
        for (int k = 0; k < 16; ++k) {
            // pivot: max |a[k]| among non-pivoted rows (uint compare of |f| bits)
            unsigned u0 = (piv0 < 0) ? __float_as_uint(fabsf(a0[k])) : 0u;
            unsigned u1 = (piv1 < 0) ? __float_as_uint(fabsf(a1[k])) : 0u;
            unsigned cu = u0 > u1 ? u0 : u1;
            unsigned bv = __reduce_max_sync(segmask, cu);
            unsigned bal = __ballot_sync(FULL, (cu == bv) && (piv0 < 0 || piv1 < 0));
            int  bl    = __ffs(bal & segmask) - 1 - segbase;   // group-local pivot lane
            bool isSrc = (q == bl);
            bool sl    = !(piv0 < 0 && u0 == bv);              // pivot slot on src lane

            float pv = __shfl_sync(FULL, sl ? a1[k]   : a0[k],   bl, 8);
            int   vb = __shfl_sync(FULL, sl ? virt1   : virt0,   bl, 8);
            neg ^= (vb != k);
            bool isp0 = isSrc && !sl;
            bool isp1 = isSrc &&  sl;
            if (virt0 == k) virt0 = vb;
            if (virt1 == k) virt1 = vb;
            if (isp0) virt0 = k;
            if (isp1) virt1 = k;

            det *= pv;
            float rpv = fast_rcp(pv);
            float m0 = (piv0 < 0 && !isp0) ? a0[k] * rpv : 0.0f;
            float m1 = (piv1 < 0 && !isp1) ? a1[k] * rpv : 0.0f;
            if (isp0) { piv0 = k; rd0 = rpv; }
            if (isp1) { piv1 = k; rd1 = rpv; }

            #pragma unroll
            for (int j = k + 1; j < 16; ++j) {
                float pj = __shfl_sync(FULL, sl ? a1[j] : a0[j], bl, 8);
                a0[j] -= m0 * pj;
                a1[j] -= m1 * pj;
            }
            #pragma unroll
            for (int j = 0; j < 16; ++j) {
                float pj = __shfl_sync(FULL, sl ? y1[j] : y0[j], bl, 8);
                y0[j] -= m0 * pj;
                y1[j] -= m1 * pj;
            }
        }

        // ---- back substitution (scale folded into coef via rdiag) ----
        #pragma unroll
        for (int k = 15; k >= 0; --k) {
            bool h0 = (piv0 == k), h1 = (piv1 == k);
            unsigned bal = __ballot_sync(FULL, h0 || h1);
            int  src = __ffs(bal & segmask) - 1 - segbase;
            bool sl  = !h0;                                    // slot on src lane
            float rk = __shfl_sync(FULL, sl ? rd1 : rd0, src, 8);
            float c0 = (piv0 < k) ? a0[k] * rk : 0.0f;
            float c1 = (piv1 < k) ? a1[k] * rk : 0.0f;
            #pragma unroll
            for (int j = 0; j < 16; ++j) {
                float xk = __shfl_sync(FULL, sl ? y1[j] : y0[j], src, 8);
                y0[j] -= c0 * xk;
                y1[j] -= c1 * xk;
            }
            if (h0) t += y0[k] * rd0;      // X[k][k]
            if (h1) t += y1[k] * rd1;
        }

        // ---- reduce trace in group, combine spins across adjacent segments ----
        float tr = t;
        tr += __shfl_xor_sync(FULL, tr, 4, 8);
        tr += __shfl_xor_sync(FULL, tr, 2, 8);
        tr += __shfl_xor_sync(FULL, tr, 1, 8);
        float sdet = neg ? -det : det;

        float tro  = __shfl_xor_sync(FULL, tr,   8, 16);   // other spin
        float deto = __shfl_xor_sync(FULL, sdet, 8, 16);
        float dp  = sdet * deto;
        float kin = -0.5f * (tr + tro) * dp;

        if ((lane & 15) == 0) {
            out[(size_t)b * NCONF + c] = kin;
            out[(size_t)(NBATCH * NCONF) + (size_t)b * NCONF + c] = dp;
        }
    }
}

extern "C" void kernel_launch(void* const* d_in, const int* in_sizes, int n_in,
                              void* d_out, int out_size) {
    (void)in_sizes; (void)n_in; (void)out_size;
    kinetic_kernel<<<NBATCH, 256>>>(
        (const float*)d_in[0],   // MO
        (const float*)d_in[1],   // d2MO
        (const float*)d_in[2],   // dJdMO
        (const float*)d_in[3],   // d2JMO
        (const int*)  d_in[4],   // cup
        (const int*)  d_in[5],   // cdown
        (float*)d_out);
}

// round 6
// speedup vs baseline: 2.0276x; 2.0276x over previous
#include <cuda_runtime.h>

#define NUPD   16
#define NMO    64
#define NCONF  64
#define NBATCH 4096
#define NELEC  32
#define RS     65   // padded shared row stride (floats) -> conflict-free gathers

__device__ __forceinline__ float fast_rcp(float x) {
    float r;
    asm("rcp.approx.f32 %0, %1;" : "=f"(r) : "f"(x));
    return r * (2.0f - x * r);   // one Newton step -> ~1 ulp
}

__global__ void __launch_bounds__(256) kinetic_kernel(
    const float* __restrict__ MO,
    const float* __restrict__ d2MO,
    const float* __restrict__ dJdMO,
    const float* __restrict__ d2JMO,
    const int*   __restrict__ cup,
    const int*   __restrict__ cdown,
    float*       __restrict__ out)   // [kinetic (B,NCONF) | det_prod (B,NCONF)]
{
    __shared__ float sM[NELEC * RS];
    __shared__ float sB[NELEC * RS];
    __shared__ int   sCfg[2 * NCONF * NUPD];

    const int b   = blockIdx.x;
    const int tid = threadIdx.x;

    // ---- stage configs ----
    for (int i = tid; i < NCONF * NUPD; i += 256) {
        sCfg[i]                = cup[i];
        sCfg[NCONF * NUPD + i] = cdown[i];
    }

    // ---- stage MO rows + fused B = d2MO + 2*dJdMO + d2JMO ----
    const size_t base = (size_t)b * (NELEC * NMO);
    const float4* gM = (const float4*)(MO    + base);
    const float4* gX = (const float4*)(d2MO  + base);
    const float4* gY = (const float4*)(dJdMO + base);
    const float4* gZ = (const float4*)(d2JMO + base);
    #pragma unroll
    for (int r = 0; r < 2; ++r) {
        int i   = tid + r * 256;
        int row = i >> 4;
        int c4  = i & 15;
        float4 m = gM[i], x = gX[i], w = gY[i], z = gZ[i];
        float* pm = &sM[row * RS + c4 * 4];
        pm[0] = m.x; pm[1] = m.y; pm[2] = m.z; pm[3] = m.w;
        float* pb = &sB[row * RS + c4 * 4];
        pb[0] = x.x + 2.0f * w.x + z.x;
        pb[1] = x.y + 2.0f * w.y + z.y;
        pb[2] = x.z + 2.0f * w.z + z.z;
        pb[3] = x.w + 2.0f * w.w + z.w;
    }
    __syncthreads();

    // ---- warp layout: 2 sixteen-lane groups per warp = (up, down) of one config ----
    const int lane = tid & 31;
    const int warp = tid >> 5;
    const int half = lane >> 4;         // 0: up, 1: down
    const int l    = lane & 15;         // my row of the 16x16 system
    const unsigned FULL = 0xFFFFFFFFu;
    const unsigned segmask = half ? 0xFFFF0000u : 0x0000FFFFu;

    const float* myM   = &sM[(half * NUPD + l) * RS];
    const float* myB   = &sB[(half * NUPD + l) * RS];
    const int*   myCfg = &sCfg[half * (NCONF * NUPD)];

    #pragma unroll 1
    for (int it = 0; it < 8; ++it) {
        const int c = warp + it * 8;

        // gather my row of A and B (stride-65 -> distinct banks across lanes)
        float a[16], y[16];
        #pragma unroll
        for (int j = 0; j < 16; ++j) {
            int cj = myCfg[c * NUPD + j];
            a[j] = myM[cj];
            y[j] = myB[cj];
        }

        // ---- Gauss-Jordan with partial pivoting on augmented [A | B] ----
        // At step k the pivot row eliminates column k from ALL other rows
        // (pivoted rows included) -> no back-substitution pass needed.
        int   pivstep = -1;
        float det   = 1.0f;
        float rdiag = 1.0f;
        int   virt  = l;        // virtual row position (permutation parity)
        bool  neg   = false;

        #pragma unroll
        for (int k = 0; k < 16; ++k) {
            // pivot: max |a[k]| among not-yet-pivoted rows (uint bits of |f|)
            unsigned cand = (pivstep < 0) ? __float_as_uint(fabsf(a[k])) : 0u;
            unsigned bv   = __reduce_max_sync(segmask, cand);
            unsigned bal  = __ballot_sync(FULL, (cand == bv) && (pivstep < 0));
            int bl = __ffs(half ? (bal >> 16) : (bal & 0xFFFFu)) - 1;

            float pv = __shfl_sync(FULL, a[k], bl, 16);
            int   vb = __shfl_sync(FULL, virt, bl, 16);
            neg ^= (vb != k);
            bool ispiv = (l == bl);
            if (virt == k) virt = vb;
            if (ispiv)     virt = k;

            det *= pv;
            float rpv = fast_rcp(pv);
            if (ispiv) { pivstep = k; rdiag = rpv; }

            // all non-pivot rows eliminate column k
            float m = ispiv ? 0.0f : a[k] * rpv;
            #pragma unroll
            for (int j = k + 1; j < 16; ++j)
                a[j] -= m * __shfl_sync(FULL, a[j], bl, 16);
            #pragma unroll
            for (int j = 0; j < 16; ++j)
                y[j] -= m * __shfl_sync(FULL, y[j], bl, 16);
        }

        // my trace contribution: X[k][k] = y[k] / u_kk for my pivot step k
        // (static unrolled select avoids dynamic register indexing -> no spills)
        float t = 0.0f;
        #pragma unroll
        for (int j = 0; j < 16; ++j)
            t += (pivstep == j) ? y[j] : 0.0f;
        t *= rdiag;

        // ---- reduce trace within group, combine spins across halves ----
        float tr = t;
        #pragma unroll
        for (int off = 8; off; off >>= 1)
            tr += __shfl_xor_sync(FULL, tr, off, 16);
        float sdet = neg ? -det : det;

        float tro  = __shfl_xor_sync(FULL, tr,   16);   // other spin
        float deto = __shfl_xor_sync(FULL, sdet, 16);
        float dp   = sdet * deto;
        float kin  = -0.5f * (tr + tro) * dp;

        if (lane == 0) {
            out[(size_t)b * NCONF + c] = kin;
            out[(size_t)(NBATCH * NCONF) + (size_t)b * NCONF + c] = dp;
        }
    }
}

extern "C" void kernel_launch(void* const* d_in, const int* in_sizes, int n_in,
                              void* d_out, int out_size) {
    (void)in_sizes; (void)n_in; (void)out_size;
    kinetic_kernel<<<NBATCH, 256>>>(
        (const float*)d_in[0],   // MO
        (const float*)d_in[1],   // d2MO
        (const float*)d_in[2],   // dJdMO
        (const float*)d_in[3],   // d2JMO
        (const int*)  d_in[4],   // cup
        (const int*)  d_in[5],   // cdown
        (float*)d_out);
}

// round 9
// speedup vs baseline: 2.7787x; 1.3705x over previous
#include <cuda_runtime.h>

#define NUPD   16
#define NMO    64
#define NCONF  64
#define NBATCH 4096
#define NELEC  32
#define RS     65   // padded shared row stride (floats) -> conflict-free gathers

__device__ __forceinline__ float fast_rcp(float x) {
    float r;
    asm("rcp.approx.f32 %0, %1;" : "=f"(r) : "f"(x));
    return r * (2.0f - x * r);   // one Newton step -> ~1 ulp
}

__global__ void __launch_bounds__(256) kinetic_kernel(
    const float* __restrict__ MO,
    const float* __restrict__ d2MO,
    const float* __restrict__ dJdMO,
    const float* __restrict__ d2JMO,
    const int*   __restrict__ cup,
    const int*   __restrict__ cdown,
    float*       __restrict__ out)   // [kinetic (B,NCONF) | det_prod (B,NCONF)]
{
    __shared__ float sM[NELEC * RS];
    __shared__ float sB[NELEC * RS];
    __shared__ int   sCfg[2 * NCONF * NUPD];

    const int b   = blockIdx.x;
    const int tid = threadIdx.x;

    // ---- stage configs ----
    for (int i = tid; i < NCONF * NUPD; i += 256) {
        sCfg[i]                = cup[i];
        sCfg[NCONF * NUPD + i] = cdown[i];
    }

    // ---- stage MO rows + fused B = d2MO + 2*dJdMO + d2JMO ----
    const size_t base = (size_t)b * (NELEC * NMO);
    const float4* gM = (const float4*)(MO    + base);
    const float4* gX = (const float4*)(d2MO  + base);
    const float4* gY = (const float4*)(dJdMO + base);
    const float4* gZ = (const float4*)(d2JMO + base);
    #pragma unroll
    for (int r = 0; r < 2; ++r) {
        int i   = tid + r * 256;
        int row = i >> 4;
        int c4  = i & 15;
        float4 m = gM[i], x = gX[i], w = gY[i], z4 = gZ[i];
        float* pm = &sM[row * RS + c4 * 4];
        pm[0] = m.x; pm[1] = m.y; pm[2] = m.z; pm[3] = m.w;
        float* pb = &sB[row * RS + c4 * 4];
        pb[0] = x.x + 2.0f * w.x + z4.x;
        pb[1] = x.y + 2.0f * w.y + z4.y;
        pb[2] = x.z + 2.0f * w.z + z4.z;
        pb[3] = x.w + 2.0f * w.w + z4.w;
    }
    __syncthreads();

    // ---- warp layout: 2 sixteen-lane groups per warp = (up, down) of one config ----
    const int lane = tid & 31;
    const int warp = tid >> 5;
    const int half = lane >> 4;         // 0: up, 1: down
    const int l    = lane & 15;         // my row of the 16x16 system
    const unsigned FULL = 0xFFFFFFFFu;
    const unsigned segmask = half ? 0xFFFF0000u : 0x0000FFFFu;

    const float* myM   = &sM[(half * NUPD + l) * RS];
    const float* bRows = &sB[(half * NUPD) * RS];      // row 0 of my spin's B
    const int*   myCfg = &sCfg[half * (NCONF * NUPD)];

    #pragma unroll 1
    for (int it = 0; it < 8; ++it) {
        const int c = warp + it * 8;

        // gather my row of A only (B is consumed at the end, straight from smem)
        float a[16];
        #pragma unroll
        for (int j = 0; j < 16; ++j)
            a[j] = myM[myCfg[c * NUPD + j]];

        // ---- Gauss-Jordan on A, tracking T (row-op transform) in pivot-step
        //      coordinates: z[t] = coeff of pivot-row-t's seed in my row of T.
        //      At step s only t<s entries are live -> triangular shuffle cost.
        float z[16];
        int   pivstep = -1;
        float det   = 1.0f;
        float rdiag = 1.0f;
        int   virt  = l;        // virtual row position (permutation parity)
        bool  neg   = false;
        unsigned permLo = 0u, permHi = 0u;   // nibble s -> pivot lane of step s

        #pragma unroll
        for (int s = 0; s < 16; ++s) {
            // pivot: max |a[s]| among non-pivoted rows; lane id packed in low
            // 4 bits of the key so REDUX alone yields the pivot lane.
            unsigned cand = (pivstep < 0)
                ? ((__float_as_uint(fabsf(a[s])) & 0xFFFFFFF0u) | (unsigned)l)
                : 0u;
            unsigned key = __reduce_max_sync(segmask, cand);
            int bl = key & 15;

            float pv = __shfl_sync(FULL, a[s], bl, 16);
            int   vb = __shfl_sync(FULL, virt, bl, 16);
            neg ^= (vb != s);
            bool ispiv = (l == bl);
            if (virt == s) virt = vb;
            if (ispiv)     virt = s;

            det *= pv;
            float rpv = fast_rcp(pv);
            if (ispiv) {
                pivstep = s; rdiag = rpv;
                if (s < 8) permLo |= (unsigned)l << (4 * s);
                else       permHi |= (unsigned)l << (4 * (s - 8));
            }
            float m = ispiv ? 0.0f : a[s] * rpv;

            #pragma unroll
            for (int j = s + 1; j < 16; ++j)
                a[j] -= m * __shfl_sync(FULL, a[j], bl, 16);
            #pragma unroll
            for (int t = 0; t < 16; ++t)
                if (t < s)
                    z[t] -= m * __shfl_sync(FULL, z[t], bl, 16);
            z[s] = (ispiv ? 1.0f : 0.0f) - m;   // pivot seed or -multiplier
        }
        permLo = __reduce_or_sync(segmask, permLo);
        permHi = __reduce_or_sync(segmask, permHi);

        // ---- trace: tr = sum_l rdiag_l * sum_t z[t] * B[p_t][pivstep_l] ----
        const int col = myCfg[c * NUPD + pivstep];   // my invA-row's B column
        float acc = 0.0f;
        #pragma unroll
        for (int t = 0; t < 16; ++t) {
            int pt = (int)((t < 8 ? (permLo >> (4 * t))
                                  : (permHi >> (4 * (t - 8)))) & 15u);
            acc += z[t] * bRows[pt * RS + col];
        }
        float tcontrib = acc * rdiag;

        // ---- reduce trace within group, combine spins across halves ----
        float tr = tcontrib;
        #pragma unroll
        for (int off = 8; off; off >>= 1)
            tr += __shfl_xor_sync(FULL, tr, off, 16);
        float sdet = neg ? -det : det;

        float tro  = __shfl_xor_sync(FULL, tr,   16);   // other spin
        float deto = __shfl_xor_sync(FULL, sdet, 16);
        float dp   = sdet * deto;
        float kin  = -0.5f * (tr + tro) * dp;

        if (lane == 0) {
            out[(size_t)b * NCONF + c] = kin;
            out[(size_t)(NBATCH * NCONF) + (size_t)b * NCONF + c] = dp;
        }
    }
}

extern "C" void kernel_launch(void* const* d_in, const int* in_sizes, int n_in,
                              void* d_out, int out_size) {
    (void)in_sizes; (void)n_in; (void)out_size;
    kinetic_kernel<<<NBATCH, 256>>>(
        (const float*)d_in[0],   // MO
        (const float*)d_in[1],   // d2MO
        (const float*)d_in[2],   // dJdMO
        (const float*)d_in[3],   // d2JMO
        (const int*)  d_in[4],   // cup
        (const int*)  d_in[5],   // cdown
        (float*)d_out);
}